// round 17
// baseline (speedup 1.0000x reference)
#include <cuda_runtime.h>
#include <cuda_bf16.h>

#define C_CLASSES 5
#define NREP 4   // weight-table replicas, stride 8 words

__device__ double   g_acc[2];   // [0]=num, [1]=den. Zero-init at load; last block resets.
__device__ unsigned g_count;    // blocks-done counter. Zero-init; last block resets.

// Fit exact quartic through (i, f[i]), i=0..4 (Newton differences -> monomial).
__device__ __forceinline__ void fit4(const float* f, float* c) {
    float d1[4], d2[3], d3[2], d4;
    #pragma unroll
    for (int i = 0; i < 4; i++) d1[i] = f[i + 1] - f[i];
    #pragma unroll
    for (int i = 0; i < 3; i++) d2[i] = (d1[i + 1] - d1[i]) * 0.5f;
    #pragma unroll
    for (int i = 0; i < 2; i++) d3[i] = (d2[i + 1] - d2[i]) * (1.0f / 3.0f);
    d4 = (d3[1] - d3[0]) * 0.25f;
    float a1 = d1[0], a2 = d2[0], a3 = d3[0], a4 = d4;
    c[0] = f[0];
    c[1] = a1 - a2 + 2.0f * a3 - 6.0f * a4;
    c[2] = a2 - 3.0f * a3 + 11.0f * a4;
    c[3] = a3 - 6.0f * a4;
    c[4] = a4;
}

// ip(x) = alpha + beta*x + sum_k gamma[k]*|x-k|   (exact PWL interp, LDS-free)
// p(t)  = exact quartic (Horner, LDS-free)
// w(t)  = single LDS.32 from replicated table
#define OWE(x_, t_, nm, dn) do {                                         \
    float _x = (x_);                                                      \
    float ip = fmaf(be, _x, al);                                          \
    ip = fmaf(g0, fabsf(_x),        ip);                                  \
    ip = fmaf(g1, fabsf(_x - 1.0f), ip);                                  \
    ip = fmaf(g2, fabsf(_x - 2.0f), ip);                                  \
    ip = fmaf(g3, fabsf(_x - 3.0f), ip);                                  \
    ip = fmaf(g4, fabsf(_x - 4.0f), ip);                                  \
    int   _t = (t_);                                                      \
    float tf = (float)_t;                                                 \
    float p  = fmaf(fmaf(fmaf(fmaf(pa4, tf, pa3), tf, pa2), tf, pa1), tf, pa0); \
    float w  = tw[_t];                                                    \
    float d  = ip - p;                                                    \
    nm = fmaf(d * d, w, nm);                                              \
    dn += w;                                                              \
} while (0)

#define ELEM4(xv, tv, nm, dn) \
    OWE((xv).x, (tv).x, nm, dn); \
    OWE((xv).y, (tv).y, nm, dn); \
    OWE((xv).z, (tv).z, nm, dn); \
    OWE((xv).w, (tv).w, nm, dn);

__global__ void __launch_bounds__(256, 5)
owe_kernel(const float4* __restrict__ inp4,
           const int4*  __restrict__ tgt4,
           const float* __restrict__ weight,
           const float* __restrict__ dist,
           int n4,
           const float* __restrict__ inp_tail,
           const int*   __restrict__ tgt_tail,
           int tail_start, int n_total,
           float* __restrict__ out) {
    __shared__ float s_coef[12];       // [0..6] al,be,g0..g4; [7..11] p quartic
    __shared__ float s_tw[NREP * 8];   // weight[t], replicated

    if (threadIdx.x == 0) {
        float ds[C_CLASSES], cs[C_CLASSES];
        float ext[C_CLASSES + 2], s[C_CLASSES + 1];
        float c = 0.f;
        #pragma unroll
        for (int k = 0; k < C_CLASSES; k++) { ds[k] = dist[k]; c += ds[k]; cs[k] = c; }
        float inv = 1.0f / (2.0f * cs[C_CLASSES - 1] - ds[0] - ds[C_CLASSES - 1]);
        ext[0] = -1.0f / (float)(C_CLASSES - 1);
        #pragma unroll
        for (int k = 0; k < C_CLASSES; k++)
            ext[k + 1] = (2.0f * cs[k] - ds[k] - ds[0]) * inv;
        ext[C_CLASSES + 1] = (float)C_CLASSES / (float)(C_CLASSES - 1);
        #pragma unroll
        for (int j = 0; j <= C_CLASSES; j++)
            s[j] = ext[j + 1] - ext[j];
        float gs = 0.0f;
        #pragma unroll
        for (int k = 0; k < C_CLASSES; k++) {
            float g = 0.5f * (s[k + 1] - s[k]);
            s_coef[2 + k] = g;
            gs += g * (float)k;
        }
        s_coef[1] = 0.5f * (s[0] + s[C_CLASSES]);
        s_coef[0] = ext[1] - gs;
        // Exact quartic for pcnl[t].
        float P[C_CLASSES], cp[5];
        #pragma unroll
        for (int k = 0; k < C_CLASSES; k++) P[k] = ext[k + 1];
        fit4(P, cp);
        #pragma unroll
        for (int k = 0; k < 5; k++) s_coef[7 + k] = cp[k];
        // Weight table, replicated.
        #pragma unroll
        for (int r = 0; r < NREP; r++) {
            #pragma unroll
            for (int k = 0; k < C_CLASSES; k++)
                s_tw[r * 8 + k] = weight[k];
        }
    }
    __syncthreads();

    const float al  = s_coef[0];
    const float be  = s_coef[1];
    const float g0  = s_coef[2];
    const float g1  = s_coef[3];
    const float g2  = s_coef[4];
    const float g3  = s_coef[5];
    const float g4  = s_coef[6];
    const float pa0 = s_coef[7],  pa1 = s_coef[8],  pa2 = s_coef[9];
    const float pa3 = s_coef[10], pa4 = s_coef[11];

    const float* __restrict__ tw = s_tw + (threadIdx.x & (NREP - 1)) * 8;

    float num0 = 0.0f, num1 = 0.0f, num2 = 0.0f, num3 = 0.0f;
    float den0 = 0.0f, den1 = 0.0f, den2 = 0.0f, den3 = 0.0f;

    int tid    = blockIdx.x * blockDim.x + threadIdx.x;
    int stride = gridDim.x * blockDim.x;

    int i = tid;
    // Unroll x4: 8 LDG.128 front-batched (MLP_p1 = 8).
    for (; i + 3 * stride < n4; i += 4 * stride) {
        float4 x0 = inp4[i];
        float4 x1 = inp4[i + stride];
        float4 x2 = inp4[i + 2 * stride];
        float4 x3 = inp4[i + 3 * stride];
        int4   t0 = tgt4[i];
        int4   t1 = tgt4[i + stride];
        int4   t2 = tgt4[i + 2 * stride];
        int4   t3 = tgt4[i + 3 * stride];
        ELEM4(x0, t0, num0, den0)
        ELEM4(x1, t1, num1, den1)
        ELEM4(x2, t2, num2, den2)
        ELEM4(x3, t3, num3, den3)
    }
    for (; i < n4; i += stride) {
        float4 x0 = inp4[i];
        int4   t0 = tgt4[i];
        ELEM4(x0, t0, num0, den0)
    }
    for (int jj = tail_start + tid; jj < n_total; jj += stride) {
        OWE(inp_tail[jj], tgt_tail[jj], num1, den1);
    }

    float num = (num0 + num1) + (num2 + num3);
    float den = (den0 + den1) + (den2 + den3);

    // Warp reduction
    #pragma unroll
    for (int off = 16; off > 0; off >>= 1) {
        num += __shfl_down_sync(0xFFFFFFFFu, num, off);
        den += __shfl_down_sync(0xFFFFFFFFu, den, off);
    }

    // Block reduction
    __shared__ float s_num[8];
    __shared__ float s_den[8];
    int lane = threadIdx.x & 31;
    int warp = threadIdx.x >> 5;
    if (lane == 0) { s_num[warp] = num; s_den[warp] = den; }
    __syncthreads();
    if (warp == 0) {
        float bn = (lane < (blockDim.x >> 5)) ? s_num[lane] : 0.0f;
        float bd = (lane < (blockDim.x >> 5)) ? s_den[lane] : 0.0f;
        #pragma unroll
        for (int off = 4; off > 0; off >>= 1) {
            bn += __shfl_down_sync(0xFFFFFFFFu, bn, off);
            bd += __shfl_down_sync(0xFFFFFFFFu, bd, off);
        }
        if (lane == 0) {
            atomicAdd(&g_acc[0], (double)bn);
            atomicAdd(&g_acc[1], (double)bd);
            __threadfence();
            unsigned done = atomicAdd(&g_count, 1u);
            if (done == gridDim.x - 1) {
                double fn = __longlong_as_double(
                    atomicExch((unsigned long long*)&g_acc[0], 0ULL));
                double fd = __longlong_as_double(
                    atomicExch((unsigned long long*)&g_acc[1], 0ULL));
                out[0] = (float)(fn / fd);
                atomicExch(&g_count, 0u);
            }
        }
    }
}

extern "C" void kernel_launch(void* const* d_in, const int* in_sizes, int n_in,
                              void* d_out, int out_size) {
    const float* inp  = (const float*)d_in[0];
    const int*   tgt  = (const int*)d_in[1];
    const float* wgt  = (const float*)d_in[2];
    const float* dist = (const float*)d_in[3];
    float* out = (float*)d_out;

    int n  = in_sizes[0];
    int n4 = n >> 2;
    int tail_start = n4 << 2;

    const int threads = 256;
    int blocks = 148 * 5;   // 740 blocks, single wave at 5 blocks/SM
    int max_useful = (n4 + threads - 1) / threads;
    if (blocks > max_useful && max_useful > 0) blocks = max_useful;
    if (blocks < 1) blocks = 1;

    owe_kernel<<<blocks, threads>>>((const float4*)inp, (const int4*)tgt,
                                    wgt, dist, n4, inp, tgt, tail_start, n, out);
}